// round 6
// baseline (speedup 1.0000x reference)
#include <cuda_runtime.h>
#include <cuda_fp16.h>
#include <cstdint>

#define EPS         1e-8f
#define NT          512
#define C_DIM       32000
#define CHUNK_F4    2000                 // float4 per chunk
#define CHUNK_BYTES 32000                // 2000 * 16
#define GRID        304                  // 2 CTAs per SM x 152 SMs
#define LOG2E       1.4426950408889634f

__device__ __forceinline__ unsigned int smem_u32(const void* p) {
    return (unsigned int)__cvta_generic_to_shared(p);
}

__device__ __forceinline__ void mbar_wait(unsigned int mb, unsigned int parity) {
    asm volatile(
        "{\n\t"
        ".reg .pred P;\n\t"
        "WAIT_%=:\n\t"
        "mbarrier.try_wait.parity.acquire.cta.shared::cta.b64 P, [%0], %1, 0x989680;\n\t"
        "@P bra DONE_%=;\n\t"
        "bra WAIT_%=;\n\t"
        "DONE_%=:\n\t"
        "}"
        :: "r"(mb), "r"(parity) : "memory");
}

__device__ __forceinline__ void tma_issue(unsigned int mb, unsigned int dst,
                                          const float* src) {
    asm volatile("mbarrier.arrive.expect_tx.shared.b64 _, [%0], %1;"
                 :: "r"(mb), "r"((unsigned int)CHUNK_BYTES) : "memory");
    asm volatile("cp.async.bulk.shared::cluster.global.mbarrier::complete_tx::bytes "
                 "[%0], [%1], %2, [%3];"
                 :: "r"(dst), "l"(src), "r"((unsigned int)CHUNK_BYTES), "r"(mb)
                 : "memory");
}

// exp(x + EPS) = exp2(x*log2e + EPS*log2e): one FFMA + one MUFU.EX2
__device__ __forceinline__ float expe(float x) {
    return exp2f(fmaf(x, LOG2E, EPS * LOG2E));
}

__global__ __launch_bounds__(NT, 2)
void smsoftmax_kernel(const float* __restrict__ logits,
                      const float* __restrict__ dist,
                      float* __restrict__ out, int B) {
    extern __shared__ float4 buf[];              // 2 x CHUNK_F4 float4 = 64000 B
    __shared__ __align__(8) unsigned long long mbar[2];
    __shared__ float red[16];
    __shared__ float bcast;

    const int tid  = threadIdx.x;
    const int lane = tid & 31;
    const int wid  = tid >> 5;
    const int bid  = blockIdx.x;

    unsigned int mb[2]  = { smem_u32(&mbar[0]), smem_u32(&mbar[1]) };
    unsigned int dst[2] = { smem_u32(buf), smem_u32(buf) + CHUNK_BYTES };

    const int nrows = (bid < B) ? (B - bid + GRID - 1) / GRID : 0;
    const int totq  = nrows * 4;                 // 4 chunks per row

    if (tid == 0) {
        asm volatile("mbarrier.init.shared.b64 [%0], 1;" :: "r"(mb[0]) : "memory");
        asm volatile("mbarrier.init.shared.b64 [%0], 1;" :: "r"(mb[1]) : "memory");
    }
    __syncthreads();

    // Prologue: prime both chunk buffers.
    if (tid == 0) {
        for (int q = 0; q < 2 && q < totq; q++) {
            int row = bid + (q >> 2) * GRID;
            const float* src = logits + (size_t)row * C_DIM + (size_t)(q & 3) * (CHUNK_F4 * 4);
            tma_issue(mb[q & 1], dst[q & 1], src);
        }
    }

    const float c   = __expf(-__ldg(dist));
    const float cm1 = c - 1.0f;
    unsigned int p0 = 0, p1 = 0;

    float   s = 0.0f;
    __half2 eh[32];                              // fp16 e for one full row

    for (int q = 0; q < totq; q++) {
        const int b     = q & 1;
        const int cslot = q & 3;

        // ---- wait chunk, fused drain + exp + partial sum, pack to fp16 ----
        if (b == 0) { mbar_wait(mb[0], p0); p0 ^= 1u; }
        else        { mbar_wait(mb[1], p1); p1 ^= 1u; }

        const float4* __restrict__ cb = buf + b * CHUNK_F4;
        #pragma unroll
        for (int j = 0; j < 4; j++) {
            int idx = j * NT + tid;
            if (idx < CHUNK_F4) {
                float4 t = cb[idx];
                float ex = expe(t.x), ey = expe(t.y);
                float ez = expe(t.z), ew = expe(t.w);
                s += (ex + ey) + (ez + ew);
                eh[(cslot * 4 + j) * 2]     = __floats2half2_rn(ex, ey);
                eh[(cslot * 4 + j) * 2 + 1] = __floats2half2_rn(ez, ew);
            }
        }
        __syncthreads();                         // buffer fully drained

        // ---- prefetch chunk q+2 into this buffer ----
        if (tid == 0 && q + 2 < totq) {
            int qq = q + 2;
            int row = bid + (qq >> 2) * GRID;
            const float* src = logits + (size_t)qq % 4 * 0 // (placeholder avoided)
                               + (size_t)row * C_DIM + (size_t)(qq & 3) * (CHUNK_F4 * 4);
            tma_issue(mb[b], dst[b], src);
        }

        if (cslot == 3) {
            // ---- block-reduce sum (16 warps) ----
            float r = s;
            #pragma unroll
            for (int o = 16; o > 0; o >>= 1)
                r += __shfl_xor_sync(0xffffffffu, r, o);
            if (lane == 0) red[wid] = r;
            __syncthreads();
            if (wid == 0) {
                float t = (lane < 16) ? red[lane] : 0.0f;
                #pragma unroll
                for (int o = 8; o > 0; o >>= 1)
                    t += __shfl_xor_sync(0xffffffffu, t, o);
                if (lane == 0) bcast = t;
            }
            __syncthreads();
            const float sp = bcast + EPS;        // s + EPS

            // ---- epilogue: out = c*e / ((c-1)*e + s + EPS), from fp16 regs ----
            const int row = bid + (q >> 2) * GRID;
            float4* __restrict__ out4 = (float4*)(out + (size_t)row * C_DIM);
            #pragma unroll
            for (int cs = 0; cs < 4; cs++) {
                #pragma unroll
                for (int j = 0; j < 4; j++) {
                    int idx = j * NT + tid;
                    if (idx < CHUNK_F4) {
                        float2 lo = __half22float2(eh[(cs * 4 + j) * 2]);
                        float2 hi = __half22float2(eh[(cs * 4 + j) * 2 + 1]);
                        float4 o;
                        o.x = __fdividef(c * lo.x, fmaf(cm1, lo.x, sp));
                        o.y = __fdividef(c * lo.y, fmaf(cm1, lo.y, sp));
                        o.z = __fdividef(c * hi.x, fmaf(cm1, hi.x, sp));
                        o.w = __fdividef(c * hi.y, fmaf(cm1, hi.y, sp));
                        out4[cs * CHUNK_F4 + idx] = o;
                    }
                }
            }
            s = 0.0f;
        }
    }
}

extern "C" void kernel_launch(void* const* d_in, const int* in_sizes, int n_in,
                              void* d_out, int out_size) {
    const float* logits = (const float*)d_in[0];
    const float* dist   = (const float*)d_in[1];
    float* out = (float*)d_out;

    const int B = in_sizes[0] / C_DIM;           // 4096 rows
    const size_t smem = 2 * (size_t)CHUNK_BYTES; // 64000 B per CTA

    cudaFuncSetAttribute(smsoftmax_kernel,
                         cudaFuncAttributeMaxDynamicSharedMemorySize, (int)smem);
    smsoftmax_kernel<<<GRID, NT, smem>>>(logits, dist, out, B);
}

// round 7
// speedup vs baseline: 1.1371x; 1.1371x over previous
#include <cuda_runtime.h>
#include <cuda_fp16.h>
#include <cstdint>

#define EPS         1e-8f
#define NT          512
#define C_DIM       32000
#define CHUNK_F4    2000                 // float4 per chunk
#define CHUNK_F     8000                 // floats per chunk
#define CHUNK_BYTES 32000                // 2000 * 16
#define GRID        304                  // 2 CTAs per SM x 152 SMs
#define LOG2E       1.4426950408889634f

__device__ __forceinline__ unsigned int smem_u32(const void* p) {
    return (unsigned int)__cvta_generic_to_shared(p);
}

__device__ __forceinline__ void mbar_wait(unsigned int mb, unsigned int parity) {
    asm volatile(
        "{\n\t"
        ".reg .pred P;\n\t"
        "WAIT_%=:\n\t"
        "mbarrier.try_wait.parity.acquire.cta.shared::cta.b64 P, [%0], %1, 0x989680;\n\t"
        "@P bra DONE_%=;\n\t"
        "bra WAIT_%=;\n\t"
        "DONE_%=:\n\t"
        "}"
        :: "r"(mb), "r"(parity) : "memory");
}

__device__ __forceinline__ void tma_issue(unsigned int mb, unsigned int dst,
                                          const float* src) {
    asm volatile("mbarrier.arrive.expect_tx.shared.b64 _, [%0], %1;"
                 :: "r"(mb), "r"((unsigned int)CHUNK_BYTES) : "memory");
    asm volatile("cp.async.bulk.shared::cluster.global.mbarrier::complete_tx::bytes "
                 "[%0], [%1], %2, [%3];"
                 :: "r"(dst), "l"(src), "r"((unsigned int)CHUNK_BYTES), "r"(mb)
                 : "memory");
}

// exp(x + EPS) = exp2(x*log2e + EPS*log2e): one FFMA + one MUFU.EX2
__device__ __forceinline__ float expe(float x) {
    return exp2f(fmaf(x, LOG2E, EPS * LOG2E));
}

__global__ __launch_bounds__(NT, 2)
void smsoftmax_kernel(const float* __restrict__ logits,
                      const float* __restrict__ dist,
                      float* __restrict__ out, int B) {
    extern __shared__ float4 buf[];              // 2 x CHUNK_F4 float4 = 64000 B
    __shared__ __align__(8) unsigned long long mbar[2];
    __shared__ float red[16];
    __shared__ float bcast;

    const int tid  = threadIdx.x;
    const int lane = tid & 31;
    const int wid  = tid >> 5;
    const int bid  = blockIdx.x;

    const unsigned int mb0  = smem_u32(&mbar[0]);
    const unsigned int mb1  = smem_u32(&mbar[1]);
    const unsigned int dst0 = smem_u32(buf);
    const unsigned int dst1 = dst0 + CHUNK_BYTES;

    const int nrows = (bid < B) ? (B - bid + GRID - 1) / GRID : 0;

    if (tid == 0) {
        asm volatile("mbarrier.init.shared.b64 [%0], 1;" :: "r"(mb0) : "memory");
        asm volatile("mbarrier.init.shared.b64 [%0], 1;" :: "r"(mb1) : "memory");
    }
    __syncthreads();

    // Prologue: prime both chunk buffers (chunks 0 and 1 of first row).
    if (tid == 0 && nrows > 0) {
        const float* base = logits + (size_t)bid * C_DIM;
        tma_issue(mb0, dst0, base);
        tma_issue(mb1, dst1, base + CHUNK_F);
    }

    const float c   = __expf(-__ldg(dist));
    const float cm1 = c - 1.0f;
    unsigned int p0 = 0, p1 = 0;

    __half2 eh[32];                              // fp16 e for one full row (regs)

    for (int r = 0; r < nrows; r++) {
        const int row = bid + r * GRID;
        float s = 0.0f;

        // ---- 4 chunks, fully unrolled: all eh[] indices compile-time ----
        #pragma unroll
        for (int cslot = 0; cslot < 4; cslot++) {
            const int b = cslot & 1;             // compile-time
            if (b == 0) { mbar_wait(mb0, p0); p0 ^= 1u; }
            else        { mbar_wait(mb1, p1); p1 ^= 1u; }

            const float4* __restrict__ cb = buf + b * CHUNK_F4;
            #pragma unroll
            for (int j = 0; j < 4; j++) {
                int idx = j * NT + tid;
                if (idx < CHUNK_F4) {
                    float4 t = cb[idx];
                    float ex = expe(t.x), ey = expe(t.y);
                    float ez = expe(t.z), ew = expe(t.w);
                    s += (ex + ey) + (ez + ew);
                    eh[(cslot * 4 + j) * 2]     = __floats2half2_rn(ex, ey);
                    eh[(cslot * 4 + j) * 2 + 1] = __floats2half2_rn(ez, ew);
                }
            }
            __syncthreads();                     // buffer fully drained

            // prefetch chunk (r*4 + cslot + 2) into this buffer
            if (tid == 0) {
                const int nr   = r + (cslot >= 2 ? 1 : 0);
                const int ns   = (cslot + 2) & 3;
                if (nr < nrows) {
                    const float* src = logits + (size_t)(bid + nr * GRID) * C_DIM
                                              + (size_t)ns * CHUNK_F;
                    tma_issue(b == 0 ? mb0 : mb1, b == 0 ? dst0 : dst1, src);
                }
            }
        }

        // ---- block-reduce sum (16 warps) ----
        float rr = s;
        #pragma unroll
        for (int o = 16; o > 0; o >>= 1)
            rr += __shfl_xor_sync(0xffffffffu, rr, o);
        if (lane == 0) red[wid] = rr;
        __syncthreads();
        if (wid == 0) {
            float t = (lane < 16) ? red[lane] : 0.0f;
            #pragma unroll
            for (int o = 8; o > 0; o >>= 1)
                t += __shfl_xor_sync(0xffffffffu, t, o);
            if (lane == 0) bcast = t;
        }
        __syncthreads();
        const float sp = bcast + EPS;            // s + EPS

        // ---- epilogue: out = c*e / ((c-1)*e + s + EPS), from fp16 regs ----
        float4* __restrict__ out4 = (float4*)(out + (size_t)row * C_DIM);
        #pragma unroll
        for (int cs = 0; cs < 4; cs++) {
            #pragma unroll
            for (int j = 0; j < 4; j++) {
                int idx = j * NT + tid;
                if (idx < CHUNK_F4) {
                    float2 lo = __half22float2(eh[(cs * 4 + j) * 2]);
                    float2 hi = __half22float2(eh[(cs * 4 + j) * 2 + 1]);
                    float4 o;
                    o.x = __fdividef(c * lo.x, fmaf(cm1, lo.x, sp));
                    o.y = __fdividef(c * lo.y, fmaf(cm1, lo.y, sp));
                    o.z = __fdividef(c * hi.x, fmaf(cm1, hi.x, sp));
                    o.w = __fdividef(c * hi.y, fmaf(cm1, hi.y, sp));
                    out4[cs * CHUNK_F4 + idx] = o;
                }
            }
        }
    }
}

extern "C" void kernel_launch(void* const* d_in, const int* in_sizes, int n_in,
                              void* d_out, int out_size) {
    const float* logits = (const float*)d_in[0];
    const float* dist   = (const float*)d_in[1];
    float* out = (float*)d_out;

    const int B = in_sizes[0] / C_DIM;           // 4096 rows
    const size_t smem = 2 * (size_t)CHUNK_BYTES; // 64000 B per CTA

    cudaFuncSetAttribute(smsoftmax_kernel,
                         cudaFuncAttributeMaxDynamicSharedMemorySize, (int)smem);
    smsoftmax_kernel<<<GRID, NT, smem>>>(logits, dist, out, B);
}

// round 9
// speedup vs baseline: 1.1469x; 1.0086x over previous
#include <cuda_runtime.h>
#include <cuda_fp16.h>
#include <cstdint>

#define EPS         1e-8f
#define NT          512
#define C_DIM       32000
#define CHUNK_F4    2000                 // float4 per chunk
#define CHUNK_F     8000                 // floats per chunk
#define CHUNK_BYTES 32000                // 2000 * 16
#define GRID        304                  // 2 CTAs per SM x 152 SMs
#define LOG2E       1.4426950408889634f

__device__ __forceinline__ unsigned int smem_u32(const void* p) {
    return (unsigned int)__cvta_generic_to_shared(p);
}

__device__ __forceinline__ void mbar_wait(unsigned int mb, unsigned int parity) {
    asm volatile(
        "{\n\t"
        ".reg .pred P;\n\t"
        "WAIT_%=:\n\t"
        "mbarrier.try_wait.parity.acquire.cta.shared::cta.b64 P, [%0], %1, 0x989680;\n\t"
        "@P bra DONE_%=;\n\t"
        "bra WAIT_%=;\n\t"
        "DONE_%=:\n\t"
        "}"
        :: "r"(mb), "r"(parity) : "memory");
}

__device__ __forceinline__ void tma_issue(unsigned int mb, unsigned int dst,
                                          const float* src) {
    asm volatile("mbarrier.arrive.expect_tx.shared.b64 _, [%0], %1;"
                 :: "r"(mb), "r"((unsigned int)CHUNK_BYTES) : "memory");
    asm volatile("cp.async.bulk.shared::cluster.global.mbarrier::complete_tx::bytes "
                 "[%0], [%1], %2, [%3];"
                 :: "r"(dst), "l"(src), "r"((unsigned int)CHUNK_BYTES), "r"(mb)
                 : "memory");
}

// exp(x + EPS) = exp2(x*log2e + EPS*log2e): one FFMA + one MUFU.EX2
__device__ __forceinline__ float expe(float x) {
    return exp2f(fmaf(x, LOG2E, EPS * LOG2E));
}

__global__ __launch_bounds__(NT, 2)
void smsoftmax_kernel(const float* __restrict__ logits,
                      const float* __restrict__ dist,
                      float* __restrict__ out, int B) {
    extern __shared__ float4 buf[];              // 2 x CHUNK_F4 float4 = 64000 B
    __shared__ __align__(8) unsigned long long mbar[2];
    __shared__ float red[16];
    __shared__ float bcast;

    const int tid  = threadIdx.x;
    const int lane = tid & 31;
    const int wid  = tid >> 5;
    const int bid  = blockIdx.x;

    const unsigned int mb0  = smem_u32(&mbar[0]);
    const unsigned int mb1  = smem_u32(&mbar[1]);
    const unsigned int dst0 = smem_u32(buf);
    const unsigned int dst1 = dst0 + CHUNK_BYTES;

    const int nrows = (bid < B) ? (B - bid + GRID - 1) / GRID : 0;

    if (tid == 0) {
        asm volatile("mbarrier.init.shared.b64 [%0], 1;" :: "r"(mb0) : "memory");
        asm volatile("mbarrier.init.shared.b64 [%0], 1;" :: "r"(mb1) : "memory");
    }
    __syncthreads();

    // Prologue: prime both chunk buffers (chunks 0 and 1 of first row).
    if (tid == 0 && nrows > 0) {
        const float* base = logits + (size_t)bid * C_DIM;
        tma_issue(mb0, dst0, base);
        tma_issue(mb1, dst1, base + CHUNK_F);
    }

    const float c   = __expf(-__ldg(dist));
    const float cm1 = c - 1.0f;
    unsigned int p0 = 0, p1 = 0;

    __half2 eh[32];                              // fp16 e for one full row (regs)

    for (int r = 0; r < nrows; r++) {
        const int row = bid + r * GRID;
        float s = 0.0f;

        // ---- 4 chunks, fully unrolled: all eh[] indices compile-time ----
        #pragma unroll
        for (int cslot = 0; cslot < 4; cslot++) {
            const int b = cslot & 1;             // compile-time
            if (b == 0) { mbar_wait(mb0, p0); p0 ^= 1u; }
            else        { mbar_wait(mb1, p1); p1 ^= 1u; }

            const float4* __restrict__ cb = buf + b * CHUNK_F4;
            #pragma unroll
            for (int j = 0; j < 4; j++) {
                int idx = j * NT + tid;
                if (idx < CHUNK_F4) {
                    float4 t = cb[idx];
                    float ex = expe(t.x), ey = expe(t.y);
                    float ez = expe(t.z), ew = expe(t.w);
                    s += (ex + ey) + (ez + ew);
                    eh[(cslot * 4 + j) * 2]     = __floats2half2_rn(ex, ey);
                    eh[(cslot * 4 + j) * 2 + 1] = __floats2half2_rn(ez, ew);
                }
            }
            __syncthreads();                     // buffer fully drained

            // prefetch chunk (r*4 + cslot + 2) into this buffer
            if (tid == 0) {
                const int nr   = r + (cslot >= 2 ? 1 : 0);
                const int ns   = (cslot + 2) & 3;
                if (nr < nrows) {
                    const float* src = logits + (size_t)(bid + nr * GRID) * C_DIM
                                              + (size_t)ns * CHUNK_F;
                    tma_issue(b == 0 ? mb0 : mb1, b == 0 ? dst0 : dst1, src);
                }
            }
        }

        // ---- block-reduce sum (16 warps) ----
        float rr = s;
        #pragma unroll
        for (int o = 16; o > 0; o >>= 1)
            rr += __shfl_xor_sync(0xffffffffu, rr, o);
        if (lane == 0) red[wid] = rr;
        __syncthreads();
        if (wid == 0) {
            float t = (lane < 16) ? red[lane] : 0.0f;
            #pragma unroll
            for (int o = 8; o > 0; o >>= 1)
                t += __shfl_xor_sync(0xffffffffu, t, o);
            if (lane == 0) bcast = t;
        }
        __syncthreads();

        // Per-row scalars: r0 = 1/(s+EPS); out = (c*r0*e) * (1 - cm1*r0*e)
        const float r0 = __fdividef(1.0f, bcast + EPS);
        const float a  = c * r0;
        const float bb = cm1 * r0;

        // ---- epilogue: pure FMA + STG, zero per-element MUFU ----
        float4* __restrict__ out4 = (float4*)(out + (size_t)row * C_DIM);
        #pragma unroll
        for (int cs = 0; cs < 4; cs++) {
            #pragma unroll
            for (int j = 0; j < 4; j++) {
                int idx = j * NT + tid;
                if (idx < CHUNK_F4) {
                    float2 lo = __half22float2(eh[(cs * 4 + j) * 2]);
                    float2 hi = __half22float2(eh[(cs * 4 + j) * 2 + 1]);
                    float4 o;
                    o.x = (a * lo.x) * fmaf(-bb, lo.x, 1.0f);
                    o.y = (a * lo.y) * fmaf(-bb, lo.y, 1.0f);
                    o.z = (a * hi.x) * fmaf(-bb, hi.x, 1.0f);
                    o.w = (a * hi.y) * fmaf(-bb, hi.y, 1.0f);
                    out4[cs * CHUNK_F4 + idx] = o;
                }
            }
        }
    }
}

extern "C" void kernel_launch(void* const* d_in, const int* in_sizes, int n_in,
                              void* d_out, int out_size) {
    const float* logits = (const float*)d_in[0];
    const float* dist   = (const float*)d_in[1];
    float* out = (float*)d_out;

    const int B = in_sizes[0] / C_DIM;           // 4096 rows
    const size_t smem = 2 * (size_t)CHUNK_BYTES; // 64000 B per CTA

    cudaFuncSetAttribute(smsoftmax_kernel,
                         cudaFuncAttributeMaxDynamicSharedMemorySize, (int)smem);
    smsoftmax_kernel<<<GRID, NT, smem>>>(logits, dist, out, B);
}

// round 10
// speedup vs baseline: 1.2645x; 1.1025x over previous
#include <cuda_runtime.h>
#include <cuda_fp16.h>
#include <cstdint>

#define EPS         1e-8f
#define NT          512
#define C_DIM       32000
#define CHUNK_F4    2000                 // float4 per chunk
#define CHUNK_F     8000                 // floats per chunk
#define CHUNK_BYTES 32000                // 2000 * 16
#define GRID        304                  // 2 CTAs per SM x 152 SMs
#define LOG2E       1.4426950408889634f

__device__ int g_ctr;                    // dynamic row queue head

__global__ void init_ctr_kernel() { g_ctr = GRID; }

__device__ __forceinline__ unsigned int smem_u32(const void* p) {
    return (unsigned int)__cvta_generic_to_shared(p);
}

__device__ __forceinline__ void mbar_wait(unsigned int mb, unsigned int parity) {
    asm volatile(
        "{\n\t"
        ".reg .pred P;\n\t"
        "WAIT_%=:\n\t"
        "mbarrier.try_wait.parity.acquire.cta.shared::cta.b64 P, [%0], %1, 0x989680;\n\t"
        "@P bra DONE_%=;\n\t"
        "bra WAIT_%=;\n\t"
        "DONE_%=:\n\t"
        "}"
        :: "r"(mb), "r"(parity) : "memory");
}

__device__ __forceinline__ void tma_issue(unsigned int mb, unsigned int dst,
                                          const float* src) {
    asm volatile("mbarrier.arrive.expect_tx.shared.b64 _, [%0], %1;"
                 :: "r"(mb), "r"((unsigned int)CHUNK_BYTES) : "memory");
    asm volatile("cp.async.bulk.shared::cluster.global.mbarrier::complete_tx::bytes "
                 "[%0], [%1], %2, [%3];"
                 :: "r"(dst), "l"(src), "r"((unsigned int)CHUNK_BYTES), "r"(mb)
                 : "memory");
}

// exp(x + EPS) = exp2(x*log2e + EPS*log2e): one FFMA + one MUFU.EX2
__device__ __forceinline__ float expe(float x) {
    return exp2f(fmaf(x, LOG2E, EPS * LOG2E));
}

__global__ __launch_bounds__(NT, 2)
void smsoftmax_kernel(const float* __restrict__ logits,
                      const float* __restrict__ dist,
                      float* __restrict__ out, int B) {
    extern __shared__ float4 buf[];              // 2 x CHUNK_F4 float4 = 64000 B
    __shared__ __align__(8) unsigned long long mbar[2];
    __shared__ float red[16];
    __shared__ float bcast;
    __shared__ int   sh_next;

    const int tid  = threadIdx.x;
    const int lane = tid & 31;
    const int wid  = tid >> 5;

    const unsigned int mb0  = smem_u32(&mbar[0]);
    const unsigned int mb1  = smem_u32(&mbar[1]);
    const unsigned int dst0 = smem_u32(buf);
    const unsigned int dst1 = dst0 + CHUNK_BYTES;

    if (tid == 0) {
        asm volatile("mbarrier.init.shared.b64 [%0], 1;" :: "r"(mb0) : "memory");
        asm volatile("mbarrier.init.shared.b64 [%0], 1;" :: "r"(mb1) : "memory");
    }
    __syncthreads();

    int cur = blockIdx.x;                        // static seed: rows 0..GRID-1

    // Prologue: prime both buffers with chunks 0,1 of cur.
    if (tid == 0 && cur < B) {
        const float* base = logits + (size_t)cur * C_DIM;
        tma_issue(mb0, dst0, base);
        tma_issue(mb1, dst1, base + CHUNK_F);
    }

    const float c   = __expf(-__ldg(dist));
    const float cm1 = c - 1.0f;
    unsigned int p0 = 0, p1 = 0;

    __half2 eh[32];                              // fp16 e for one full row (regs)

    int nxt = B;                                 // tid0's copy of next row

    while (cur < B) {
        float s = 0.0f;

        // ---- 4 chunks, fully unrolled: all eh[] indices compile-time ----
        #pragma unroll
        for (int cslot = 0; cslot < 4; cslot++) {
            const int b = cslot & 1;             // compile-time
            if (b == 0) { mbar_wait(mb0, p0); p0 ^= 1u; }
            else        { mbar_wait(mb1, p1); p1 ^= 1u; }

            const float4* __restrict__ cb = buf + b * CHUNK_F4;
            #pragma unroll
            for (int j = 0; j < 4; j++) {
                int idx = j * NT + tid;
                if (idx < CHUNK_F4) {
                    float4 t = cb[idx];
                    float ex = expe(t.x), ey = expe(t.y);
                    float ez = expe(t.z), ew = expe(t.w);
                    s += (ex + ey) + (ez + ew);
                    eh[(cslot * 4 + j) * 2]     = __floats2half2_rn(ex, ey);
                    eh[(cslot * 4 + j) * 2 + 1] = __floats2half2_rn(ez, ew);
                }
            }
            __syncthreads();                     // buffer fully drained

            if (tid == 0) {
                if (cslot == 0) {
                    // grab next row from the queue (latency hidden by drain)
                    nxt = atomicAdd(&g_ctr, 1);
                    sh_next = nxt;
                }
                // slots 0,1 -> chunks 2,3 of cur; slots 2,3 -> chunks 0,1 of nxt
                const int trow = (cslot < 2) ? cur : nxt;
                const int tch  = (cslot + 2) & 3;
                if (trow < B) {
                    const float* src = logits + (size_t)trow * C_DIM
                                              + (size_t)tch * CHUNK_F;
                    tma_issue(b == 0 ? mb0 : mb1, b == 0 ? dst0 : dst1, src);
                }
            }
        }

        // ---- block-reduce sum (16 warps) ----
        float rr = s;
        #pragma unroll
        for (int o = 16; o > 0; o >>= 1)
            rr += __shfl_xor_sync(0xffffffffu, rr, o);
        if (lane == 0) red[wid] = rr;
        __syncthreads();
        if (wid == 0) {
            float t = (lane < 16) ? red[lane] : 0.0f;
            #pragma unroll
            for (int o = 8; o > 0; o >>= 1)
                t += __shfl_xor_sync(0xffffffffu, t, o);
            if (lane == 0) bcast = t;
        }
        __syncthreads();

        // Per-row scalars: r0 = 1/(s+EPS); out = (c*r0*e) * (1 - cm1*r0*e)
        const float r0 = __fdividef(1.0f, bcast + EPS);
        const float a  = c * r0;
        const float bb = cm1 * r0;

        // ---- epilogue: pure FMA + STG, zero per-element MUFU ----
        float4* __restrict__ out4 = (float4*)(out + (size_t)cur * C_DIM);
        #pragma unroll
        for (int cs = 0; cs < 4; cs++) {
            #pragma unroll
            for (int j = 0; j < 4; j++) {
                int idx = j * NT + tid;
                if (idx < CHUNK_F4) {
                    float2 lo = __half22float2(eh[(cs * 4 + j) * 2]);
                    float2 hi = __half22float2(eh[(cs * 4 + j) * 2 + 1]);
                    float4 o;
                    o.x = (a * lo.x) * fmaf(-bb, lo.x, 1.0f);
                    o.y = (a * lo.y) * fmaf(-bb, lo.y, 1.0f);
                    o.z = (a * hi.x) * fmaf(-bb, hi.x, 1.0f);
                    o.w = (a * hi.y) * fmaf(-bb, hi.y, 1.0f);
                    out4[cs * CHUNK_F4 + idx] = o;
                }
            }
        }

        // advance to the dynamically-assigned next row (sh_next written at
        // slot 0 under a barrier; all threads passed >=2 barriers since)
        cur = sh_next;
    }
}

extern "C" void kernel_launch(void* const* d_in, const int* in_sizes, int n_in,
                              void* d_out, int out_size) {
    const float* logits = (const float*)d_in[0];
    const float* dist   = (const float*)d_in[1];
    float* out = (float*)d_out;

    const int B = in_sizes[0] / C_DIM;           // 4096 rows
    const size_t smem = 2 * (size_t)CHUNK_BYTES; // 64000 B per CTA

    init_ctr_kernel<<<1, 1>>>();                 // reset queue head each launch
    cudaFuncSetAttribute(smsoftmax_kernel,
                         cudaFuncAttributeMaxDynamicSharedMemorySize, (int)smem);
    smsoftmax_kernel<<<GRID, NT, smem>>>(logits, dist, out, B);
}

// round 12
// speedup vs baseline: 1.2727x; 1.0065x over previous
#include <cuda_runtime.h>
#include <cuda_fp16.h>
#include <cstdint>

#define EPS         1e-8f
#define NT          512
#define C_DIM       32000
#define CHUNK_F4    2000                 // float4 per chunk
#define CHUNK_F     8000                 // floats per chunk
#define CHUNK_BYTES 32000                // 2000 * 16
#define NBUF        3
#define GRID        304                  // 2 CTAs per SM x 152 SMs
#define LOG2E       1.4426950408889634f

__device__ int g_ctr;                    // dynamic row queue head

__global__ void init_ctr_kernel() { g_ctr = GRID; }

__device__ __forceinline__ unsigned int smem_u32(const void* p) {
    return (unsigned int)__cvta_generic_to_shared(p);
}

__device__ __forceinline__ void mbar_wait(unsigned int mb, unsigned int parity) {
    asm volatile(
        "{\n\t"
        ".reg .pred P;\n\t"
        "WAIT_%=:\n\t"
        "mbarrier.try_wait.parity.acquire.cta.shared::cta.b64 P, [%0], %1, 0x989680;\n\t"
        "@P bra DONE_%=;\n\t"
        "bra WAIT_%=;\n\t"
        "DONE_%=:\n\t"
        "}"
        :: "r"(mb), "r"(parity) : "memory");
}

__device__ __forceinline__ void tma_issue(unsigned int mb, unsigned int dst,
                                          const float* src) {
    asm volatile("mbarrier.arrive.expect_tx.shared.b64 _, [%0], %1;"
                 :: "r"(mb), "r"((unsigned int)CHUNK_BYTES) : "memory");
    asm volatile("cp.async.bulk.shared::cluster.global.mbarrier::complete_tx::bytes "
                 "[%0], [%1], %2, [%3];"
                 :: "r"(dst), "l"(src), "r"((unsigned int)CHUNK_BYTES), "r"(mb)
                 : "memory");
}

// exp(x + EPS) = exp2(x*log2e + EPS*log2e): one FFMA + one MUFU.EX2
__device__ __forceinline__ float expe(float x) {
    return exp2f(fmaf(x, LOG2E, EPS * LOG2E));
}

__global__ __launch_bounds__(NT, 2)
void smsoftmax_kernel(const float* __restrict__ logits,
                      const float* __restrict__ dist,
                      float* __restrict__ out, int B) {
    extern __shared__ float4 buf[];              // NBUF x CHUNK_F4 float4 = 96000 B
    __shared__ __align__(8) unsigned long long mbar[NBUF];
    __shared__ float red[16];
    __shared__ float bcast;
    __shared__ int   sh_next;

    const int tid  = threadIdx.x;
    const int lane = tid & 31;
    const int wid  = tid >> 5;

    const unsigned int mb_base  = smem_u32(&mbar[0]);   // mbar[i] at +8*i
    const unsigned int dst_base = smem_u32(buf);        // buffer i at +i*CHUNK_BYTES

    if (tid == 0) {
        #pragma unroll
        for (int i = 0; i < NBUF; i++)
            asm volatile("mbarrier.init.shared.b64 [%0], 1;"
                         :: "r"(mb_base + 8u * i) : "memory");
    }
    __syncthreads();

    int cur = blockIdx.x;                        // static seed: rows 0..GRID-1

    // Prologue: prime the 3 buffers with chunks 0,1,2 of cur.
    if (tid == 0 && cur < B) {
        const float* base = logits + (size_t)cur * C_DIM;
        #pragma unroll
        for (int i = 0; i < NBUF; i++)
            tma_issue(mb_base + 8u * i, dst_base + (unsigned int)i * CHUNK_BYTES,
                      base + (size_t)i * CHUNK_F);
    }

    const float c   = __expf(-__ldg(dist));
    const float cm1 = c - 1.0f;

    unsigned int pmask = 0;                      // per-buffer parity bits (runtime)
    int sb = 0;                                  // starting buffer of current row

    __half2 eh[32];                              // fp16 e for one full row (regs)

    while (cur < B) {
        float s = 0.0f;
        int nxt = B;

        #pragma unroll
        for (int cslot = 0; cslot < 4; cslot++) {
            int b = sb + cslot;                  // runtime buffer index, 0..2
            if (b >= NBUF) b -= NBUF;
            const unsigned int mba = mb_base + 8u * (unsigned int)b;

            mbar_wait(mba, (pmask >> b) & 1u);
            pmask ^= (1u << b);                  // n-th wait on b uses parity n&1

            const float4* __restrict__ cb = buf + b * CHUNK_F4;
            #pragma unroll
            for (int j = 0; j < 4; j++) {
                int idx = j * NT + tid;
                if (idx < CHUNK_F4) {
                    float4 t = cb[idx];
                    float ex = expe(t.x), ey = expe(t.y);
                    float ez = expe(t.z), ew = expe(t.w);
                    s += (ex + ey) + (ez + ew);
                    eh[(cslot * 4 + j) * 2]     = __floats2half2_rn(ex, ey);
                    eh[(cslot * 4 + j) * 2 + 1] = __floats2half2_rn(ez, ew);
                }
            }
            __syncthreads();                     // buffer fully drained by all warps

            if (tid == 0) {
                if (cslot == 0) {
                    nxt = atomicAdd(&g_ctr, 1);  // latency hidden by later drains
                    sh_next = nxt;
                }
                // refill same buffer with chunk q+3:
                //   cslot0 -> chunk3 of cur; cslots1,2,3 -> chunks 0,1,2 of nxt
                const int trow = (cslot == 0) ? cur : nxt;
                const int tch  = (cslot + 3) & 3;
                if (trow < B) {
                    const float* src = logits + (size_t)trow * C_DIM
                                              + (size_t)tch * CHUNK_F;
                    tma_issue(mba, dst_base + (unsigned int)b * CHUNK_BYTES, src);
                }
            }
        }
        sb += 1;                                 // 4 chunks advance start by 4%3 = 1
        if (sb >= NBUF) sb -= NBUF;

        // ---- block-reduce sum (16 warps) ----
        float rr = s;
        #pragma unroll
        for (int o = 16; o > 0; o >>= 1)
            rr += __shfl_xor_sync(0xffffffffu, rr, o);
        if (lane == 0) red[wid] = rr;
        __syncthreads();
        if (wid == 0) {
            float t = (lane < 16) ? red[lane] : 0.0f;
            #pragma unroll
            for (int o = 8; o > 0; o >>= 1)
                t += __shfl_xor_sync(0xffffffffu, t, o);
            if (lane == 0) bcast = t;
        }
        __syncthreads();

        // Per-row scalars: r0 = 1/(s+EPS); out = (c*r0*e) * (1 - cm1*r0*e)
        const float r0 = __fdividef(1.0f, bcast + EPS);
        const float a  = c * r0;
        const float bb = cm1 * r0;

        // ---- epilogue: pure FMA + STG (overlaps 3 in-flight next-row chunks) ----
        float4* __restrict__ out4 = (float4*)(out + (size_t)cur * C_DIM);
        #pragma unroll
        for (int cs = 0; cs < 4; cs++) {
            #pragma unroll
            for (int j = 0; j < 4; j++) {
                int idx = j * NT + tid;
                if (idx < CHUNK_F4) {
                    float2 lo = __half22float2(eh[(cs * 4 + j) * 2]);
                    float2 hi = __half22float2(eh[(cs * 4 + j) * 2 + 1]);
                    float4 o;
                    o.x = (a * lo.x) * fmaf(-bb, lo.x, 1.0f);
                    o.y = (a * lo.y) * fmaf(-bb, lo.y, 1.0f);
                    o.z = (a * hi.x) * fmaf(-bb, hi.x, 1.0f);
                    o.w = (a * hi.y) * fmaf(-bb, hi.y, 1.0f);
                    out4[cs * CHUNK_F4 + idx] = o;
                }
            }
        }

        // sh_next written at cslot0 under barriers; >=2 barriers since
        cur = sh_next;
    }
}

extern "C" void kernel_launch(void* const* d_in, const int* in_sizes, int n_in,
                              void* d_out, int out_size) {
    const float* logits = (const float*)d_in[0];
    const float* dist   = (const float*)d_in[1];
    float* out = (float*)d_out;

    const int B = in_sizes[0] / C_DIM;                 // 4096 rows
    const size_t smem = (size_t)NBUF * CHUNK_BYTES;    // 96000 B per CTA

    init_ctr_kernel<<<1, 1>>>();                       // reset queue head each launch
    cudaFuncSetAttribute(smsoftmax_kernel,
                         cudaFuncAttributeMaxDynamicSharedMemorySize, (int)smem);
    smsoftmax_kernel<<<GRID, NT, smem>>>(logits, dist, out, B);
}